// round 6
// baseline (speedup 1.0000x reference)
#include <cuda_runtime.h>
#include <cuda_bf16.h>
#include <cstdint>

#define B_   2
#define S_   2048
#define H_   16
#define D_   64
#define E_   1024
#define TE_  3072
#define MTOT (B_ * S_)   // 4096

// ---------------------------------------------------------------------------
// Scratch (__device__ globals; no allocation allowed)
// ---------------------------------------------------------------------------
__device__ __nv_bfloat16 g_qkv_hi[(size_t)MTOT * TE_];
__device__ __nv_bfloat16 g_qkv_lo[(size_t)MTOT * TE_];
__device__ __nv_bfloat16 g_o_hi[(size_t)MTOT * E_];
__device__ __nv_bfloat16 g_o_lo[(size_t)MTOT * E_];
__device__ __nv_bfloat16 g_x_hi[(size_t)MTOT * E_];
__device__ __nv_bfloat16 g_x_lo[(size_t)MTOT * E_];
__device__ __nv_bfloat16 g_wq_hi[(size_t)TE_ * E_];
__device__ __nv_bfloat16 g_wq_lo[(size_t)TE_ * E_];
__device__ __nv_bfloat16 g_wo_hi[(size_t)E_ * E_];
__device__ __nv_bfloat16 g_wo_lo[(size_t)E_ * E_];

// ---------------------------------------------------------------------------
// Helpers (sm_80-level PTX only)
// ---------------------------------------------------------------------------
__device__ __forceinline__ uint32_t smem_u32(const void* p) {
    uint32_t a;
    asm("{ .reg .u64 t; cvta.to.shared.u64 t, %1; cvt.u32.u64 %0, t; }" : "=r"(a) : "l"(p));
    return a;
}
__device__ __forceinline__ uint32_t pk2(float a, float b) {
    __nv_bfloat162 t = __floats2bfloat162_rn(a, b);
    return *reinterpret_cast<uint32_t*>(&t);
}
__device__ __forceinline__ uint32_t pkh(__nv_bfloat16 a, __nv_bfloat16 b) {
    __nv_bfloat162 t(a, b);
    return *reinterpret_cast<uint32_t*>(&t);
}
__device__ __forceinline__ void ldm_x4(uint32_t* r, uint32_t addr) {
    asm volatile("ldmatrix.sync.aligned.m8n8.x4.shared.b16 {%0,%1,%2,%3}, [%4];"
                 : "=r"(r[0]), "=r"(r[1]), "=r"(r[2]), "=r"(r[3]) : "r"(addr));
}
__device__ __forceinline__ void ldm_x4t(uint32_t* r, uint32_t addr) {
    asm volatile("ldmatrix.sync.aligned.m8n8.x4.trans.shared.b16 {%0,%1,%2,%3}, [%4];"
                 : "=r"(r[0]), "=r"(r[1]), "=r"(r[2]), "=r"(r[3]) : "r"(addr));
}
__device__ __forceinline__ void mma16816(float* c, const uint32_t* a, const uint32_t* b) {
    asm volatile(
        "mma.sync.aligned.m16n8k16.row.col.f32.bf16.bf16.f32 "
        "{%0,%1,%2,%3}, {%4,%5,%6,%7}, {%8,%9}, {%0,%1,%2,%3};"
        : "+f"(c[0]), "+f"(c[1]), "+f"(c[2]), "+f"(c[3])
        : "r"(a[0]), "r"(a[1]), "r"(a[2]), "r"(a[3]), "r"(b[0]), "r"(b[1]));
}
__device__ __forceinline__ void cp_async16(uint32_t saddr, const void* gaddr) {
    asm volatile("cp.async.cg.shared.global [%0], [%1], 16;" :: "r"(saddr), "l"(gaddr) : "memory");
}
__device__ __forceinline__ void cp_commit() {
    asm volatile("cp.async.commit_group;" ::: "memory");
}
#define CP_WAIT(n) asm volatile("cp.async.wait_group %0;" :: "n"(n) : "memory")

// 128B-row XOR swizzle (8x16B groups) — used by attention tiles
__device__ __forceinline__ uint32_t sw128(uint32_t row, uint32_t kg) {
    return row * 128u + ((kg ^ (row & 7u)) << 4);
}
// 64B-row XOR swizzle (4x16B groups) — conflict-free for ldmatrix & cp.async
__device__ __forceinline__ uint32_t sw64(uint32_t row, uint32_t kg) {
    return row * 64u + ((kg ^ ((row >> 1) & 3u)) << 4);
}

// ---------------------------------------------------------------------------
// fp32 -> bf16 hi + bf16 lo split
// ---------------------------------------------------------------------------
__global__ __launch_bounds__(256)
void split_bf16x2(const float* __restrict__ in, __nv_bfloat16* __restrict__ hi,
                  __nv_bfloat16* __restrict__ lo, int n4)
{
    int i = blockIdx.x * blockDim.x + threadIdx.x;
    if (i >= n4) return;
    float4 v = ((const float4*)in)[i];
    __nv_bfloat16 h0 = __float2bfloat16_rn(v.x);
    __nv_bfloat16 h1 = __float2bfloat16_rn(v.y);
    __nv_bfloat16 h2 = __float2bfloat16_rn(v.z);
    __nv_bfloat16 h3 = __float2bfloat16_rn(v.w);
    uint2 hp = make_uint2(pkh(h0, h1), pkh(h2, h3));
    uint2 lp = make_uint2(pk2(v.x - __bfloat162float(h0), v.y - __bfloat162float(h1)),
                          pk2(v.z - __bfloat162float(h2), v.w - __bfloat162float(h3)));
    *(uint2*)(hi + (size_t)i * 4) = hp;
    *(uint2*)(lo + (size_t)i * 4) = lp;
}

// ---------------------------------------------------------------------------
// HMMA split-bf16 GEMM (NT): C = A[M,K]*B[N,K]^T + bias
// 128x64 block tile, 8 warps (32x32 each), BK=32, 4-stage cp.async ring,
// ONE __syncthreads per K-chunk. 2 CTAs/SM.
// MODE 0: fp32 C.  MODE 1: bf16 hi/lo split outputs.
// ---------------------------------------------------------------------------
#define OA_HI 0
#define OA_LO 8192
#define OB_HI 16384
#define OB_LO 20480
#define GSTG  24576                  // one stage
#define GSMEM4 (4 * GSTG)            // 98304

__device__ __forceinline__ void gemm_issue(
    uint32_t sdst, const __nv_bfloat16* Ah, const __nv_bfloat16* Al,
    const __nv_bfloat16* Bh, const __nv_bfloat16* Bl,
    int bm, int bn, int K, int t, int c)
{
    const int koff = c * 64;           // 32 bf16 = 64 bytes
    // A chunks: ids t, 256+t, 512+t, 768+t  (tile = id>>9, row = (id>>2)&127, kg = id&3)
    #pragma unroll
    for (int i = 0; i < 4; i++) {
        const int id = i * 256 + t;
        const int row = (id >> 2) & 127;
        const int kg = id & 3;
        const __nv_bfloat16* base = (id >> 9) ? Al : Ah;
        const uint32_t so = ((id >> 9) ? OA_LO : OA_HI) + sw64(row, kg);
        cp_async16(sdst + so, (const char*)(base + (size_t)(bm + row) * K) + kg * 16 + koff);
    }
    // B chunks: ids 1024+t, 1280+t  (id2 = id-1024, tile = id2>>8, row = (id2>>2)&63, kg = id2&3)
    #pragma unroll
    for (int i = 0; i < 2; i++) {
        const int id2 = i * 256 + t;
        const int row = (id2 >> 2) & 63;
        const int kg = id2 & 3;
        const __nv_bfloat16* base = (id2 >> 8) ? Bl : Bh;
        const uint32_t so = ((id2 >> 8) ? OB_LO : OB_HI) + sw64(row, kg);
        cp_async16(sdst + so, (const char*)(base + (size_t)(bn + row) * K) + kg * 16 + koff);
    }
    cp_commit();
}

template <int MODE>
__global__ __launch_bounds__(256, 2)
void gemm_mma(const __nv_bfloat16* __restrict__ Ah, const __nv_bfloat16* __restrict__ Al,
              const __nv_bfloat16* __restrict__ Bh, const __nv_bfloat16* __restrict__ Bl,
              const float* __restrict__ bias, float* __restrict__ C,
              __nv_bfloat16* __restrict__ Chi, __nv_bfloat16* __restrict__ Clo,
              int N, int K)
{
    extern __shared__ char smem[];
    const uint32_t sb = smem_u32(smem);
    const int t = threadIdx.x;
    const int wid = t >> 5;
    const int lane = t & 31;
    const int bm = blockIdx.y * 128;
    const int bn = blockIdx.x * 64;
    const int wm = (wid >> 1) * 32;
    const int wn = (wid & 1) * 32;

    float acc[2][4][4];
    #pragma unroll
    for (int mt = 0; mt < 2; mt++)
        #pragma unroll
        for (int nt = 0; nt < 4; nt++)
            #pragma unroll
            for (int j = 0; j < 4; j++) acc[mt][nt][j] = 0.f;

    const int niter = K >> 5;   // K/32

    // prologue: stages 0,1,2
    gemm_issue(sb + 0 * GSTG, Ah, Al, Bh, Bl, bm, bn, K, t, 0);
    gemm_issue(sb + 1 * GSTG, Ah, Al, Bh, Bl, bm, bn, K, t, 1);
    gemm_issue(sb + 2 * GSTG, Ah, Al, Bh, Bl, bm, bn, K, t, 2);

    for (int c = 0; c < niter; c++) {
        CP_WAIT(2);             // in-order groups: stage c has landed
        __syncthreads();        // all warps done reading slot (c+3)&3 (= (c-1)&3)

        if (c + 3 < niter)
            gemm_issue(sb + ((c + 3) & 3) * GSTG, Ah, Al, Bh, Bl, bm, bn, K, t, c + 3);
        else
            cp_commit();        // empty group keeps wait_group arithmetic exact

        const uint32_t stage = sb + (c & 3) * GSTG;
        #pragma unroll
        for (int ks = 0; ks < 2; ks++) {
            uint32_t ah[2][4], al[2][4], bh[2][4], bl[2][4];
            #pragma unroll
            for (int mt = 0; mt < 2; mt++) {
                uint32_t off = sw64(wm + mt * 16 + (lane & 15), ks * 2 + (lane >> 4));
                ldm_x4(ah[mt], stage + OA_HI + off);
                ldm_x4(al[mt], stage + OA_LO + off);
            }
            #pragma unroll
            for (int p = 0; p < 2; p++) {   // covers nt = 2p, 2p+1
                uint32_t off = sw64(wn + (p * 2 + (lane >> 4)) * 8 + (lane & 7),
                                    ks * 2 + ((lane >> 3) & 1));
                ldm_x4(bh[p], stage + OB_HI + off);
                ldm_x4(bl[p], stage + OB_LO + off);
            }
            #pragma unroll
            for (int mt = 0; mt < 2; mt++)
                #pragma unroll
                for (int nt = 0; nt < 4; nt++) {
                    const uint32_t* bhf = &bh[nt >> 1][(nt & 1) * 2];
                    const uint32_t* blf = &bl[nt >> 1][(nt & 1) * 2];
                    mma16816(acc[mt][nt], ah[mt], bhf);
                    mma16816(acc[mt][nt], ah[mt], blf);
                    mma16816(acc[mt][nt], al[mt], bhf);
                }
        }
    }

    // epilogue
    #pragma unroll
    for (int mt = 0; mt < 2; mt++) {
        const int r0 = bm + wm + mt * 16 + (lane >> 2);
        #pragma unroll
        for (int nt = 0; nt < 4; nt++) {
            const int col = bn + wn + nt * 8 + (lane & 3) * 2;
            const float b0 = bias[col], b1 = bias[col + 1];
            float v00 = acc[mt][nt][0] + b0, v01 = acc[mt][nt][1] + b1;
            float v10 = acc[mt][nt][2] + b0, v11 = acc[mt][nt][3] + b1;
            if (MODE == 0) {
                *(float2*)&C[(size_t)r0 * N + col] = make_float2(v00, v01);
                *(float2*)&C[(size_t)(r0 + 8) * N + col] = make_float2(v10, v11);
            } else {
                __nv_bfloat16 h00 = __float2bfloat16_rn(v00);
                __nv_bfloat16 h01 = __float2bfloat16_rn(v01);
                __nv_bfloat16 h10 = __float2bfloat16_rn(v10);
                __nv_bfloat16 h11 = __float2bfloat16_rn(v11);
                *(uint32_t*)&Chi[(size_t)r0 * N + col] = pkh(h00, h01);
                *(uint32_t*)&Chi[(size_t)(r0 + 8) * N + col] = pkh(h10, h11);
                *(uint32_t*)&Clo[(size_t)r0 * N + col] =
                    pk2(v00 - __bfloat162float(h00), v01 - __bfloat162float(h01));
                *(uint32_t*)&Clo[(size_t)(r0 + 8) * N + col] =
                    pk2(v10 - __bfloat162float(h10), v11 - __bfloat162float(h11));
            }
        }
    }
}

// ---------------------------------------------------------------------------
// HMMA flash attention, pre-split bf16 inputs, cp.async double buffer.
// CTA = 64 q-rows of one (b,h), 4 warps. smem: Qh Ql + 2 stages{Kh Kl Vh Vl}.
// ---------------------------------------------------------------------------
#define AT      8192
#define ASTAGE  (4 * AT)
#define ASMEM   (2 * AT + 2 * ASTAGE)   // 81920

__device__ __forceinline__ void attn_issue_kv(uint32_t sdst, int b, int h, int kt, int t)
{
    const size_t base_off = ((size_t)(b * S_ + kt * 64) * TE_ + h * (3 * D_)) * 2;
    #pragma unroll
    for (int i = 0; i < 16; i++) {
        const int tile = i >> 2;                  // 0:Kh 1:Kl 2:Vh 3:Vl
        const int row = (i & 3) * 16 + (t >> 3);
        const int kg = t & 7;
        const __nv_bfloat16* arr = (tile & 1) ? g_qkv_lo : g_qkv_hi;
        const size_t go = base_off + (size_t)row * (TE_ * 2)
                        + (tile < 2 ? D_ : 2 * D_) * 2 + kg * 16;
        cp_async16(sdst + (uint32_t)tile * AT + sw128(row, kg), (const char*)arr + go);
    }
    cp_commit();
}

__global__ __launch_bounds__(128, 2)
void flash_mma()
{
    extern __shared__ char smem[];
    const uint32_t sb = smem_u32(smem);
    const uint32_t sQh = sb, sQl = sb + AT;

    const int t = threadIdx.x;
    const int wid = t >> 5;
    const int lane = t & 31;
    const int qt = blockIdx.x, h = blockIdx.y, b = blockIdx.z;

    {
        const size_t qbase = ((size_t)(b * S_ + qt * 64) * TE_ + h * (3 * D_)) * 2;
        #pragma unroll
        for (int i = 0; i < 8; i++) {
            const int tile = i >> 2;
            const int row = (i & 3) * 16 + (t >> 3);
            const int kg = t & 7;
            const __nv_bfloat16* arr = tile ? g_qkv_lo : g_qkv_hi;
            const size_t go = qbase + (size_t)row * (TE_ * 2) + kg * 16;
            cp_async16(sb + (uint32_t)tile * AT + sw128(row, kg), (const char*)arr + go);
        }
        cp_commit();
    }
    attn_issue_kv(sb + 2 * AT, b, h, 0, t);

    CP_WAIT(1);
    __syncthreads();

    uint32_t aqh[4][4], aql[4][4];
    #pragma unroll
    for (int ks = 0; ks < 4; ks++) {
        uint32_t off = sw128(wid * 16 + (lane & 15), ks * 2 + (lane >> 4));
        ldm_x4(aqh[ks], sQh + off);
        ldm_x4(aql[ks], sQl + off);
    }

    float o[8][4];
    #pragma unroll
    for (int nt = 0; nt < 8; nt++)
        #pragma unroll
        for (int j = 0; j < 4; j++) o[nt][j] = 0.f;
    float m0 = -1e30f, m1 = -1e30f, l0 = 0.f, l1 = 0.f;

    const int NT = S_ / 64;
    for (int kt = 0; kt < NT; kt++) {
        if (kt + 1 < NT) {
            attn_issue_kv(sb + 2 * AT + ((kt + 1) & 1) * ASTAGE, b, h, kt + 1, t);
            CP_WAIT(1);
        } else {
            CP_WAIT(0);
        }
        __syncthreads();

        const uint32_t st = sb + 2 * AT + (kt & 1) * ASTAGE;
        const uint32_t stKh = st, stKl = st + AT, stVh = st + 2 * AT, stVl = st + 3 * AT;

        // ---- S = Q K^T (3-term split, fp32 accum) ----
        float sc[8][4];
        #pragma unroll
        for (int nt = 0; nt < 8; nt++)
            #pragma unroll
            for (int j = 0; j < 4; j++) sc[nt][j] = 0.f;
        #pragma unroll
        for (int ks = 0; ks < 4; ks++) {
            #pragma unroll
            for (int p = 0; p < 4; p++) {
                uint32_t off = sw128((p * 2 + (lane >> 4)) * 8 + (lane & 7),
                                     ks * 2 + ((lane >> 3) & 1));
                uint32_t bh[4], bl[4];
                ldm_x4(bh, stKh + off);
                ldm_x4(bl, stKl + off);
                mma16816(sc[2 * p], aqh[ks], bh);
                mma16816(sc[2 * p], aqh[ks], bl);
                mma16816(sc[2 * p], aql[ks], bh);
                mma16816(sc[2 * p + 1], aqh[ks], bh + 2);
                mma16816(sc[2 * p + 1], aqh[ks], bl + 2);
                mma16816(sc[2 * p + 1], aql[ks], bh + 2);
            }
        }
        #pragma unroll
        for (int nt = 0; nt < 8; nt++) {
            sc[nt][0] *= 0.125f; sc[nt][1] *= 0.125f;
            sc[nt][2] *= 0.125f; sc[nt][3] *= 0.125f;
        }

        // ---- online softmax ----
        float rx0 = -1e30f, rx1 = -1e30f;
        #pragma unroll
        for (int nt = 0; nt < 8; nt++) {
            rx0 = fmaxf(rx0, fmaxf(sc[nt][0], sc[nt][1]));
            rx1 = fmaxf(rx1, fmaxf(sc[nt][2], sc[nt][3]));
        }
        rx0 = fmaxf(rx0, __shfl_xor_sync(0xffffffffu, rx0, 1));
        rx0 = fmaxf(rx0, __shfl_xor_sync(0xffffffffu, rx0, 2));
        rx1 = fmaxf(rx1, __shfl_xor_sync(0xffffffffu, rx1, 1));
        rx1 = fmaxf(rx1, __shfl_xor_sync(0xffffffffu, rx1, 2));

        const float mn0 = fmaxf(m0, rx0), mn1 = fmaxf(m1, rx1);
        const float s0 = __expf(m0 - mn0), s1 = __expf(m1 - mn1);
        m0 = mn0; m1 = mn1;
        #pragma unroll
        for (int nt = 0; nt < 8; nt++) {
            o[nt][0] *= s0; o[nt][1] *= s0;
            o[nt][2] *= s1; o[nt][3] *= s1;
        }
        float sum0 = 0.f, sum1 = 0.f;
        #pragma unroll
        for (int nt = 0; nt < 8; nt++) {
            sc[nt][0] = __expf(sc[nt][0] - mn0);
            sc[nt][1] = __expf(sc[nt][1] - mn0);
            sc[nt][2] = __expf(sc[nt][2] - mn1);
            sc[nt][3] = __expf(sc[nt][3] - mn1);
            sum0 += sc[nt][0] + sc[nt][1];
            sum1 += sc[nt][2] + sc[nt][3];
        }
        sum0 += __shfl_xor_sync(0xffffffffu, sum0, 1);
        sum0 += __shfl_xor_sync(0xffffffffu, sum0, 2);
        sum1 += __shfl_xor_sync(0xffffffffu, sum1, 1);
        sum1 += __shfl_xor_sync(0xffffffffu, sum1, 2);
        l0 = l0 * s0 + sum0;
        l1 = l1 * s1 + sum1;

        // ---- O += P V (3-term split) ----
        #pragma unroll
        for (int ks = 0; ks < 4; ks++) {
            uint32_t aph[4], apl[4];
            {
                const int j0 = 2 * ks, j1 = 2 * ks + 1;
                __nv_bfloat16 h00 = __float2bfloat16_rn(sc[j0][0]);
                __nv_bfloat16 h01 = __float2bfloat16_rn(sc[j0][1]);
                __nv_bfloat16 h02 = __float2bfloat16_rn(sc[j0][2]);
                __nv_bfloat16 h03 = __float2bfloat16_rn(sc[j0][3]);
                __nv_bfloat16 h10 = __float2bfloat16_rn(sc[j1][0]);
                __nv_bfloat16 h11 = __float2bfloat16_rn(sc[j1][1]);
                __nv_bfloat16 h12 = __float2bfloat16_rn(sc[j1][2]);
                __nv_bfloat16 h13 = __float2bfloat16_rn(sc[j1][3]);
                aph[0] = pkh(h00, h01);
                aph[1] = pkh(h02, h03);
                aph[2] = pkh(h10, h11);
                aph[3] = pkh(h12, h13);
                apl[0] = pk2(sc[j0][0] - __bfloat162float(h00), sc[j0][1] - __bfloat162float(h01));
                apl[1] = pk2(sc[j0][2] - __bfloat162float(h02), sc[j0][3] - __bfloat162float(h03));
                apl[2] = pk2(sc[j1][0] - __bfloat162float(h10), sc[j1][1] - __bfloat162float(h11));
                apl[3] = pk2(sc[j1][2] - __bfloat162float(h12), sc[j1][3] - __bfloat162float(h13));
            }
            #pragma unroll
            for (int p = 0; p < 4; p++) {
                uint32_t off = sw128(ks * 16 + (lane & 15), 2 * p + (lane >> 4));
                uint32_t bh[4], bl[4];
                ldm_x4t(bh, stVh + off);
                ldm_x4t(bl, stVl + off);
                mma16816(o[2 * p], aph, bh);
                mma16816(o[2 * p], aph, bl);
                mma16816(o[2 * p], apl, bh);
                mma16816(o[2 * p + 1], aph, bh + 2);
                mma16816(o[2 * p + 1], aph, bl + 2);
                mma16816(o[2 * p + 1], apl, bh + 2);
            }
        }
        __syncthreads();
    }

    // ---- normalize, split hi/lo, store ----
    const float inv0 = 1.f / l0, inv1 = 1.f / l1;
    const int r0 = b * S_ + qt * 64 + wid * 16 + (lane >> 2);
    #pragma unroll
    for (int nt = 0; nt < 8; nt++) {
        const int col = h * D_ + nt * 8 + (lane & 3) * 2;
        float v00 = o[nt][0] * inv0, v01 = o[nt][1] * inv0;
        float v10 = o[nt][2] * inv1, v11 = o[nt][3] * inv1;
        __nv_bfloat16 h00 = __float2bfloat16_rn(v00);
        __nv_bfloat16 h01 = __float2bfloat16_rn(v01);
        __nv_bfloat16 h10 = __float2bfloat16_rn(v10);
        __nv_bfloat16 h11 = __float2bfloat16_rn(v11);
        *(uint32_t*)&g_o_hi[(size_t)r0 * E_ + col] = pkh(h00, h01);
        *(uint32_t*)&g_o_hi[(size_t)(r0 + 8) * E_ + col] = pkh(h10, h11);
        *(uint32_t*)&g_o_lo[(size_t)r0 * E_ + col] =
            pk2(v00 - __bfloat162float(h00), v01 - __bfloat162float(h01));
        *(uint32_t*)&g_o_lo[(size_t)(r0 + 8) * E_ + col] =
            pk2(v10 - __bfloat162float(h10), v11 - __bfloat162float(h11));
    }
}

// ---------------------------------------------------------------------------
// Launch
// ---------------------------------------------------------------------------
extern "C" void kernel_launch(void* const* d_in, const int* in_sizes, int n_in,
                              void* d_out, int out_size)
{
    const float* x     = (const float*)d_in[0];
    const float* w_qkv = (const float*)d_in[1];
    const float* b_qkv = (const float*)d_in[2];
    const float* w_o   = (const float*)d_in[3];
    const float* b_o   = (const float*)d_in[4];
    float* out = (float*)d_out;

    __nv_bfloat16 *qkv_hi, *qkv_lo, *o_hi, *o_lo;
    __nv_bfloat16 *x_hi, *x_lo, *wq_hi, *wq_lo, *wo_hi, *wo_lo;
    cudaGetSymbolAddress((void**)&qkv_hi, g_qkv_hi);
    cudaGetSymbolAddress((void**)&qkv_lo, g_qkv_lo);
    cudaGetSymbolAddress((void**)&o_hi, g_o_hi);
    cudaGetSymbolAddress((void**)&o_lo, g_o_lo);
    cudaGetSymbolAddress((void**)&x_hi, g_x_hi);
    cudaGetSymbolAddress((void**)&x_lo, g_x_lo);
    cudaGetSymbolAddress((void**)&wq_hi, g_wq_hi);
    cudaGetSymbolAddress((void**)&wq_lo, g_wq_lo);
    cudaGetSymbolAddress((void**)&wo_hi, g_wo_hi);
    cudaGetSymbolAddress((void**)&wo_lo, g_wo_lo);

    cudaFuncSetAttribute(gemm_mma<0>, cudaFuncAttributeMaxDynamicSharedMemorySize, GSMEM4);
    cudaFuncSetAttribute(gemm_mma<1>, cudaFuncAttributeMaxDynamicSharedMemorySize, GSMEM4);
    cudaFuncSetAttribute(flash_mma, cudaFuncAttributeMaxDynamicSharedMemorySize, ASMEM);

    {
        int n4 = (MTOT * E_) / 4;
        split_bf16x2<<<(n4 + 255) / 256, 256>>>(x, x_hi, x_lo, n4);
        n4 = (TE_ * E_) / 4;
        split_bf16x2<<<(n4 + 255) / 256, 256>>>(w_qkv, wq_hi, wq_lo, n4);
        n4 = (E_ * E_) / 4;
        split_bf16x2<<<(n4 + 255) / 256, 256>>>(w_o, wo_hi, wo_lo, n4);
    }

    {
        dim3 g(TE_ / 64, MTOT / 128);    // 48 x 32
        gemm_mma<1><<<g, 256, GSMEM4>>>(x_hi, x_lo, wq_hi, wq_lo, b_qkv,
                                        nullptr, qkv_hi, qkv_lo, TE_, E_);
    }
    {
        dim3 g(S_ / 64, H_, B_);          // 32 x 16 x 2
        flash_mma<<<g, 128, ASMEM>>>();
    }
    {
        dim3 g(E_ / 64, MTOT / 128);      // 16 x 32
        gemm_mma<0><<<g, 256, GSMEM4>>>(o_hi, o_lo, wo_hi, wo_lo, b_o,
                                        out, nullptr, nullptr, E_, E_);
    }
}